// round 12
// baseline (speedup 1.0000x reference)
#include <cuda_runtime.h>
#include <math.h>
#include <stdint.h>

#define MP      20
#define TSTEPS  199
#define BATCH   2048
#define MTILE   16
#define NCTA    128
#define NTHR    512

typedef unsigned long long ull;

// preprocessed weights (cat k-axis: x 0:32 | y 32:64 | z 64:128 | h 128:384)
__device__ float dWA[384*512];   // enc1 | pri1
__device__ float dWB[256*512];   // enc2 | pri2
__device__ float dWC[256*256];   // em|es|pm|ps
__device__ float dWD[384*256];   // dec1
__device__ float dWE[256*256];   // dec2
__device__ float dWF[256*64];    // dm|ds
__device__ float dWih[128*768];  // GRU input (cat rows 0:128)
__device__ float dWhh[256*768];  // GRU hidden (cat rows 128:384)
__device__ float dBA[512], dBB[512], dBC[256], dBD[256], dBE[256], dBF[64];
__device__ double dPart[NCTA*2];
__device__ unsigned int dCount;

__device__ __forceinline__ ull pk2(float a, float b) {
    ull r; asm("mov.b64 %0, {%1, %2};" : "=l"(r) : "f"(a), "f"(b)); return r;
}
__device__ __forceinline__ void upk2(ull v, float& a, float& b) {
    asm("mov.b64 {%0, %1}, %2;" : "=f"(a), "=f"(b) : "l"(v));
}
__device__ __forceinline__ void fma2(ull& d, ull a, ull b) {
    asm("fma.rn.f32x2 %0, %1, %2, %0;" : "+l"(d) : "l"(a), "l"(b));
}
__device__ __forceinline__ float sp(float x) { return (x > 15.f) ? x : log1pf(expf(x)); }
__device__ __forceinline__ float sigm(float x) { return 1.f / (1.f + expf(-x)); }

// Two output columns (n0, n1) over 8 batch rows starting at m0.
// Both columns read the SAME activation block (warp-broadcast LDS), so each
// 16B activation load feeds 8 fma2 (ratio 4:1).
template<int KLEN, int KC, bool RELU>
__device__ __forceinline__ void gemm2(const float* __restrict__ W, int NW,
                                      int n0, int n1, int kstart,
                                      float b0, float b1,
                                      const float* __restrict__ actS, int m0,
                                      float* __restrict__ o0,
                                      float* __restrict__ o1)
{
    ull acc0[4], acc1[4];
    {
        ull p0 = pk2(b0, b0), p1 = pk2(b1, b1);
        #pragma unroll
        for (int i = 0; i < 4; ++i) { acc0[i] = p0; acc1[i] = p1; }
    }
    const float* Wp = W + (size_t)kstart * NW;
    const float* Ap = actS + (size_t)kstart * MP + m0;
    #pragma unroll 1
    for (int k0 = 0; k0 < KLEN; k0 += KC) {
        float w0[KC], w1[KC];
        #pragma unroll
        for (int kk = 0; kk < KC; ++kk) {
            const float* wr = Wp + (size_t)(k0 + kk) * NW;
            w0[kk] = __ldg(wr + n0);
            w1[kk] = __ldg(wr + n1);
        }
        #pragma unroll
        for (int kk = 0; kk < KC; ++kk) {
            const float* ar = Ap + (k0 + kk) * MP;
            ulonglong2 a0 = *reinterpret_cast<const ulonglong2*>(ar);
            ulonglong2 a1 = *reinterpret_cast<const ulonglong2*>(ar + 4);
            ull w20 = pk2(w0[kk], w0[kk]);
            ull w21 = pk2(w1[kk], w1[kk]);
            fma2(acc0[0], w20, a0.x); fma2(acc0[1], w20, a0.y);
            fma2(acc0[2], w20, a1.x); fma2(acc0[3], w20, a1.y);
            fma2(acc1[0], w21, a0.x); fma2(acc1[1], w21, a0.y);
            fma2(acc1[2], w21, a1.x); fma2(acc1[3], w21, a1.y);
        }
    }
    #pragma unroll
    for (int i = 0; i < 4; ++i) {
        float lo, hi; upk2(acc0[i], lo, hi);
        if (RELU) { lo = fmaxf(lo, 0.f); hi = fmaxf(hi, 0.f); }
        *reinterpret_cast<float2*>(o0 + m0 + 2 * i) = make_float2(lo, hi);
    }
    #pragma unroll
    for (int i = 0; i < 4; ++i) {
        float lo, hi; upk2(acc1[i], lo, hi);
        if (RELU) { lo = fmaxf(lo, 0.f); hi = fmaxf(hi, 0.f); }
        *reinterpret_cast<float2*>(o1 + m0 + 2 * i) = make_float2(lo, hi);
    }
}

// dst[n][0:16] += src[n][0:16] (optional relu), n < N
template<bool RELU>
__device__ __forceinline__ void combine(float* __restrict__ dst,
                                        const float* __restrict__ src,
                                        int N, int tid)
{
    for (int i = tid; i < N * 8; i += NTHR) {
        int n = i >> 3, mp = (i & 7) * 2;
        float2 d = *reinterpret_cast<float2*>(dst + n * MP + mp);
        float2 s = *reinterpret_cast<const float2*>(src + n * MP + mp);
        d.x += s.x; d.y += s.y;
        if (RELU) { d.x = fmaxf(d.x, 0.f); d.y = fmaxf(d.y, 0.f); }
        *reinterpret_cast<float2*>(dst + n * MP + mp) = d;
    }
}

#define TOTAL_PREP 870208

__global__ void vrnn_prep(
    const float* __restrict__ enc_w1, const float* __restrict__ enc_b1,
    const float* __restrict__ enc_w2, const float* __restrict__ enc_b2,
    const float* __restrict__ enc_mw, const float* __restrict__ enc_mb,
    const float* __restrict__ enc_sw, const float* __restrict__ enc_sb,
    const float* __restrict__ pri_w1, const float* __restrict__ pri_b1,
    const float* __restrict__ pri_w2, const float* __restrict__ pri_b2,
    const float* __restrict__ pri_mw, const float* __restrict__ pri_mb,
    const float* __restrict__ pri_sw, const float* __restrict__ pri_sb,
    const float* __restrict__ dec_w1, const float* __restrict__ dec_b1,
    const float* __restrict__ dec_w2, const float* __restrict__ dec_b2,
    const float* __restrict__ dec_mw, const float* __restrict__ dec_mb,
    const float* __restrict__ dec_sw, const float* __restrict__ dec_sb,
    const float* __restrict__ wih,    const float* __restrict__ whh)
{
    int j = blockIdx.x * blockDim.x + threadIdx.x;
    if (j == 0) dCount = 0;
    if (j >= TOTAL_PREP) return;

    if (j < 384*512) {                 // WA: enc1(n<256) | pri1
        int k = j / 512, n = j % 512;
        float v = 0.f;
        if (n < 256) {                 // enc in [x,y,h]
            if (k < 64)        v = enc_w1[n*320 + k];
            else if (k >= 128) v = enc_w1[n*320 + k - 64];
        } else {                       // pri in [y,h]
            int q = n - 256;
            if (k >= 32 && k < 64) v = pri_w1[q*288 + k - 32];
            else if (k >= 128)     v = pri_w1[q*288 + k - 96];
        }
        dWA[j] = v; return;
    }
    j -= 384*512;
    if (j < 256*512) {
        int k = j / 512, n = j % 512;
        dWB[j] = (n < 256) ? enc_w2[n*256 + k] : pri_w2[(n-256)*256 + k];
        return;
    }
    j -= 256*512;
    if (j < 256*256) {
        int k = j / 256, n = j % 256;
        float v;
        if      (n < 64)  v = enc_mw[n*256 + k];
        else if (n < 128) v = enc_sw[(n-64)*256 + k];
        else if (n < 192) v = pri_mw[(n-128)*256 + k];
        else              v = pri_sw[(n-192)*256 + k];
        dWC[j] = v; return;
    }
    j -= 256*256;
    if (j < 384*256) {                 // dec in [y,z,h]: c = k-32 for k>=32
        int k = j / 256, n = j % 256;
        dWD[j] = (k >= 32) ? dec_w1[n*352 + k - 32] : 0.f;
        return;
    }
    j -= 384*256;
    if (j < 256*256) {
        int k = j / 256, n = j % 256;
        dWE[j] = dec_w2[n*256 + k]; return;
    }
    j -= 256*256;
    if (j < 256*64) {
        int k = j / 64, n = j % 64;
        dWF[j] = (n < 32) ? dec_mw[n*256 + k] : dec_sw[(n-32)*256 + k];
        return;
    }
    j -= 256*64;
    if (j < 128*768) {                 // GRU in [x,z]
        int k = j / 768, n = j % 768;
        float v = 0.f;
        if (k < 32)       v = wih[n*96 + k];
        else if (k >= 64) v = wih[n*96 + k - 32];
        dWih[j] = v; return;
    }
    j -= 128*768;
    if (j < 256*768) {
        int k = j / 768, n = j % 768;
        dWhh[j] = whh[n*256 + k]; return;
    }
    j -= 256*768;
    if (j < 512) { dBA[j] = (j < 256) ? enc_b1[j] : pri_b1[j-256]; return; }
    j -= 512;
    if (j < 512) { dBB[j] = (j < 256) ? enc_b2[j] : pri_b2[j-256]; return; }
    j -= 512;
    if (j < 256) {
        dBC[j] = (j < 64) ? enc_mb[j] : (j < 128) ? enc_sb[j-64]
               : (j < 192) ? pri_mb[j-128] : pri_sb[j-192];
        return;
    }
    j -= 256;
    if (j < 256) { dBD[j] = dec_b1[j]; return; }
    j -= 256;
    if (j < 256) { dBE[j] = dec_b2[j]; return; }
    j -= 256;
    dBF[j] = (j < 32) ? dec_mb[j] : dec_sb[j-32];
}

__global__ void __launch_bounds__(NTHR, 1)
vrnn_main(const float* __restrict__ states, const float* __restrict__ eps,
          const float* __restrict__ gbih,   const float* __restrict__ gbhh,
          float* __restrict__ out)
{
    extern __shared__ float sm[];
    float* CAT = sm;              // [384][MP]
    float* L1  = sm + 7680;       // [512][MP]
    float* L2  = sm + 17920;      // [512][MP]
    float* HB  = sm + 28160;      // [256][MP]

    const int tid  = threadIdx.x;
    const int row0 = blockIdx.x * MTILE;

    for (int i = tid; i < 7680; i += NTHR) CAT[i] = 0.f;  // zero z & h
    __syncthreads();

    // hoisted GRU biases (thread-role constants)
    const int gn = tid & 255;
    const float g_br = gbih[gn] + gbhh[gn];
    const float g_bz = gbih[256 + gn] + gbhh[256 + gn];
    const float g_bi = gbih[512 + gn];
    const float g_bh = gbhh[512 + gn];

    double klacc = 0.0, nllacc = 0.0;

    for (int t = 0; t < TSTEPS; ++t) {
        {   // load x=states[t+1], y=states[t], transposed to [k][m]
            const float* yb = states + ((size_t)t       * BATCH + row0) * 32;
            const float* xb = states + ((size_t)(t + 1) * BATCH + row0) * 32;
            int r = tid >> 5, c = tid & 31;
            CAT[c * MP + r]        = xb[r * 32 + c];
            CAT[(32 + c) * MP + r] = yb[r * 32 + c];
        }
        __syncthreads();

        // A: enc1|pri1  N=512 K=384 — cols (p, p+256), m-split, direct epilogue
        {
            int p = tid & 255, m0 = (tid >> 8) * 8;
            gemm2<384, 8, true>(dWA, 512, p, p + 256, 0, dBA[p], dBA[p + 256],
                                CAT, m0, L1 + p * MP, L1 + (p + 256) * MP);
        }
        __syncthreads();

        // B: enc2|pri2  N=512 K=256 — cols (n, n+128) within enc/pri half
        {
            int pp = tid & 255, m0 = (tid >> 8) * 8;
            int n0 = (pp < 128) ? pp : pp + 128;
            const float* act = L1 + ((pp < 128) ? 0 : 256 * MP);
            gemm2<256, 8, true>(dWB, 512, n0, n0 + 128, 0, dBB[n0], dBB[n0 + 128],
                                act, m0, L2 + n0 * MP, L2 + (n0 + 128) * MP);
        }
        __syncthreads();

        // C: heads em|es|pm|ps  N=256 K=256 — cols (q,q+64) in-half, k-split x2
        {
            int q = tid & 127, m0 = ((tid >> 7) & 1) * 8, kt = tid >> 8;
            int n0 = (q < 64) ? q : q + 64;
            const float* act = L2 + ((q < 64) ? 0 : 256 * MP);
            float* ob = kt ? L1 : HB;
            gemm2<128, 8, false>(dWC, 256, n0, n0 + 64, kt * 128,
                                 kt ? 0.f : dBC[n0], kt ? 0.f : dBC[n0 + 64],
                                 act, m0, ob + n0 * MP, ob + (n0 + 64) * MP);
        }
        __syncthreads();
        combine<false>(HB, L1, 256, tid);
        __syncthreads();

        {   // z = em + softplus(es)*eps; KL
            int n = tid & 63, mg = (tid >> 6) * 2;
            const float* eb = eps + ((size_t)t * BATCH + row0) * 64;
            float kls = 0.f;
            #pragma unroll
            for (int jj = 0; jj < 2; ++jj) {
                int m = mg + jj;
                float em = HB[n * MP + m];
                float es = sp(HB[(64  + n) * MP + m]);
                float pm = HB[(128 + n) * MP + m];
                float ps = sp(HB[(192 + n) * MP + m]);
                float e  = eb[m * 64 + n];
                CAT[(64 + n) * MP + m] = fmaf(es, e, em);
                float d = em - pm;
                kls += 2.f * (logf(ps) - logf(es)) + (es * es + d * d) / (ps * ps) - 1.f;
            }
            klacc += 0.5 * (double)kls;
        }
        __syncthreads();

        // D: dec1  N=256 K=384 — cols (q,q+128), k-split x2, partials in L1
        {
            int q = tid & 127, m0 = ((tid >> 7) & 1) * 8, kt = tid >> 8;
            float* ob = L1 + kt * 256 * MP;
            gemm2<192, 8, false>(dWD, 256, q, q + 128, kt * 192,
                                 kt ? 0.f : dBD[q], kt ? 0.f : dBD[q + 128],
                                 CAT, m0, ob + q * MP, ob + (q + 128) * MP);
        }
        __syncthreads();
        combine<true>(L1, L1 + 256 * MP, 256, tid);
        __syncthreads();

        // E: dec2  N=256 K=256 — cols (q,q+128), k-split x2, partials in L2
        {
            int q = tid & 127, m0 = ((tid >> 7) & 1) * 8, kt = tid >> 8;
            float* ob = L2 + kt * 256 * MP;
            gemm2<128, 8, false>(dWE, 256, q, q + 128, kt * 128,
                                 kt ? 0.f : dBE[q], kt ? 0.f : dBE[q + 128],
                                 L1, m0, ob + q * MP, ob + (q + 128) * MP);
        }
        __syncthreads();
        combine<true>(L2, L2 + 256 * MP, 256, tid);
        __syncthreads();

        // F: dm|ds  N=64 K=256 — cols (f,f+32), k-split x8, partials in L1
        {
            int f = tid & 31, m0 = ((tid >> 5) & 1) * 8, kt = tid >> 6;
            float* ob = L1 + kt * 64 * MP;
            gemm2<32, 8, false>(dWF, 64, f, f + 32, kt * 32,
                                kt ? 0.f : dBF[f], kt ? 0.f : dBF[f + 32],
                                L2, m0, ob + f * MP, ob + (f + 32) * MP);
        }
        __syncthreads();
        {   // F combine 8-way -> HB (512 items, one per thread)
            int n = tid >> 3, mp = (tid & 7) * 2;
            float2 s = *reinterpret_cast<float2*>(L1 + n * MP + mp);
            #pragma unroll
            for (int b = 1; b < 8; ++b) {
                float2 p = *reinterpret_cast<float2*>(L1 + b * 64 * MP + n * MP + mp);
                s.x += p.x; s.y += p.y;
            }
            *reinterpret_cast<float2*>(HB + n * MP + mp) = s;
        }
        __syncthreads();

        {   // NLL
            int n = tid & 31, m = tid >> 5;
            float dm = HB[n * MP + m];
            float ds = sp(HB[(32 + n) * MP + m]);
            float dd = CAT[n * MP + m] - dm;
            nllacc += (double)(logf(ds) + dd * dd / (2.f * ds * ds)
                               + 0.91893853320467274f);
        }

        {   // fused GRU: gi + gh + gates; thread = (n 0..255, m-half)
            const int n = gn;
            const int m0 = (tid >> 8) * 8;
            ull ar[4], az[4], ai[4], ah[4];
            {
                ull r0 = pk2(g_br, g_br), z0 = pk2(g_bz, g_bz);
                ull i0 = pk2(g_bi, g_bi), h0 = pk2(g_bh, g_bh);
                #pragma unroll
                for (int i = 0; i < 4; ++i) { ar[i]=r0; az[i]=z0; ai[i]=i0; ah[i]=h0; }
            }
            #pragma unroll 1
            for (int k0 = 0; k0 < 128; k0 += 8) {        // input part, cat[0:128)
                float wr[8], wz[8], wn[8];
                #pragma unroll
                for (int kk = 0; kk < 8; ++kk) {
                    const float* wp = dWih + (size_t)(k0 + kk) * 768;
                    wr[kk] = __ldg(wp + n);
                    wz[kk] = __ldg(wp + 256 + n);
                    wn[kk] = __ldg(wp + 512 + n);
                }
                #pragma unroll
                for (int kk = 0; kk < 8; ++kk) {
                    const float* a = CAT + (k0 + kk) * MP + m0;
                    ulonglong2 a0 = *reinterpret_cast<const ulonglong2*>(a);
                    ulonglong2 a1 = *reinterpret_cast<const ulonglong2*>(a + 4);
                    ull wr2 = pk2(wr[kk], wr[kk]);
                    ull wz2 = pk2(wz[kk], wz[kk]);
                    ull wn2 = pk2(wn[kk], wn[kk]);
                    fma2(ar[0],wr2,a0.x); fma2(ar[1],wr2,a0.y);
                    fma2(ar[2],wr2,a1.x); fma2(ar[3],wr2,a1.y);
                    fma2(az[0],wz2,a0.x); fma2(az[1],wz2,a0.y);
                    fma2(az[2],wz2,a1.x); fma2(az[3],wz2,a1.y);
                    fma2(ai[0],wn2,a0.x); fma2(ai[1],wn2,a0.y);
                    fma2(ai[2],wn2,a1.x); fma2(ai[3],wn2,a1.y);
                }
            }
            #pragma unroll 1
            for (int k0 = 0; k0 < 256; k0 += 8) {        // hidden part, cat[128:384)
                float wr[8], wz[8], wn[8];
                #pragma unroll
                for (int kk = 0; kk < 8; ++kk) {
                    const float* wp = dWhh + (size_t)(k0 + kk) * 768;
                    wr[kk] = __ldg(wp + n);
                    wz[kk] = __ldg(wp + 256 + n);
                    wn[kk] = __ldg(wp + 512 + n);
                }
                #pragma unroll
                for (int kk = 0; kk < 8; ++kk) {
                    const float* a = CAT + (128 + k0 + kk) * MP + m0;
                    ulonglong2 a0 = *reinterpret_cast<const ulonglong2*>(a);
                    ulonglong2 a1 = *reinterpret_cast<const ulonglong2*>(a + 4);
                    ull wr2 = pk2(wr[kk], wr[kk]);
                    ull wz2 = pk2(wz[kk], wz[kk]);
                    ull wn2 = pk2(wn[kk], wn[kk]);
                    fma2(ar[0],wr2,a0.x); fma2(ar[1],wr2,a0.y);
                    fma2(ar[2],wr2,a1.x); fma2(ar[3],wr2,a1.y);
                    fma2(az[0],wz2,a0.x); fma2(az[1],wz2,a0.y);
                    fma2(az[2],wz2,a1.x); fma2(az[3],wz2,a1.y);
                    fma2(ah[0],wn2,a0.x); fma2(ah[1],wn2,a0.y);
                    fma2(ah[2],wn2,a1.x); fma2(ah[3],wn2,a1.y);
                }
            }
            float hold[8];
            #pragma unroll
            for (int m = 0; m < 8; ++m) hold[m] = CAT[(128 + n) * MP + m0 + m];
            __syncthreads();   // all reads of old h / x / z done
            #pragma unroll
            for (int i = 0; i < 4; ++i) {
                float rA, rB, uA, uB, iA, iB, hA, hB;
                upk2(ar[i], rA, rB); upk2(az[i], uA, uB);
                upk2(ai[i], iA, iB); upk2(ah[i], hA, hB);
                rA = sigm(rA); rB = sigm(rB);
                uA = sigm(uA); uB = sigm(uB);
                float nA = tanhf(iA + rA * hA);
                float nB = tanhf(iB + rB * hB);
                CAT[(128 + n) * MP + m0 + 2*i]     = (1.f - uA) * nA + uA * hold[2*i];
                CAT[(128 + n) * MP + m0 + 2*i + 1] = (1.f - uB) * nB + uB * hold[2*i + 1];
            }
            __syncthreads();
        }
    }

    // deterministic block reduction of losses
    double* red = reinterpret_cast<double*>(sm);
    red[tid] = klacc; red[NTHR + tid] = nllacc;
    __syncthreads();
    for (int s = NTHR / 2; s > 0; s >>= 1) {
        if (tid < s) { red[tid] += red[tid + s]; red[NTHR + tid] += red[NTHR + tid + s]; }
        __syncthreads();
    }
    if (tid == 0) {
        dPart[blockIdx.x * 2]     = red[0];
        dPart[blockIdx.x * 2 + 1] = red[NTHR];
        __threadfence();
        atomicAdd(&dCount, 1u);
        if (blockIdx.x == 0) {   // grid=128 <= SM count, 1 CTA/SM: all resident
            while (atomicAdd(&dCount, 0u) < (unsigned)gridDim.x) { __nanosleep(200); }
            double kl = 0.0, nl = 0.0;
            for (int i = 0; i < NCTA; ++i) { kl += dPart[2*i]; nl += dPart[2*i+1]; }
            out[0] = (float)kl; out[1] = (float)nl;
        }
    }
}

extern "C" void kernel_launch(void* const* d_in, const int* in_sizes, int n_in,
                              void* d_out, int out_size) {
    const float* states = (const float*)d_in[0];
    const float* eps    = (const float*)d_in[1];
    const float *enc_w1 = (const float*)d_in[2],  *enc_b1 = (const float*)d_in[3];
    const float *enc_w2 = (const float*)d_in[4],  *enc_b2 = (const float*)d_in[5];
    const float *enc_mw = (const float*)d_in[6],  *enc_mb = (const float*)d_in[7];
    const float *enc_sw = (const float*)d_in[8],  *enc_sb = (const float*)d_in[9];
    const float *pri_w1 = (const float*)d_in[10], *pri_b1 = (const float*)d_in[11];
    const float *pri_w2 = (const float*)d_in[12], *pri_b2 = (const float*)d_in[13];
    const float *pri_mw = (const float*)d_in[14], *pri_mb = (const float*)d_in[15];
    const float *pri_sw = (const float*)d_in[16], *pri_sb = (const float*)d_in[17];
    const float *dec_w1 = (const float*)d_in[18], *dec_b1 = (const float*)d_in[19];
    const float *dec_w2 = (const float*)d_in[20], *dec_b2 = (const float*)d_in[21];
    const float *dec_mw = (const float*)d_in[22], *dec_mb = (const float*)d_in[23];
    const float *dec_sw = (const float*)d_in[24], *dec_sb = (const float*)d_in[25];
    const float *gwih   = (const float*)d_in[26], *gwhh   = (const float*)d_in[27];
    const float *gbih   = (const float*)d_in[28], *gbhh   = (const float*)d_in[29];
    float* out = (float*)d_out;

    static bool attrSet = false;
    if (!attrSet) {
        cudaFuncSetAttribute(vrnn_main, cudaFuncAttributeMaxDynamicSharedMemorySize,
                             33280 * (int)sizeof(float));
        attrSet = true;
    }

    vrnn_prep<<<(TOTAL_PREP + 255) / 256, 256>>>(
        enc_w1, enc_b1, enc_w2, enc_b2, enc_mw, enc_mb, enc_sw, enc_sb,
        pri_w1, pri_b1, pri_w2, pri_b2, pri_mw, pri_mb, pri_sw, pri_sb,
        dec_w1, dec_b1, dec_w2, dec_b2, dec_mw, dec_mb, dec_sw, dec_sb,
        gwih, gwhh);
    vrnn_main<<<NCTA, NTHR, 33280 * sizeof(float)>>>(states, eps, gbih, gbhh, out);
}

// round 13
// speedup vs baseline: 1.0005x; 1.0005x over previous
#include <cuda_runtime.h>
#include <math.h>
#include <stdint.h>

#define MP      20
#define TSTEPS  199
#define BATCH   2048
#define MTILE   16
#define NCTA    128
#define NTHR    512

typedef unsigned long long ull;

// preprocessed weights (cat k-axis: x 0:32 | y 32:64 | z 64:128 | h 128:384)
__device__ float dWA[384*512];   // enc1 | pri1
__device__ float dWB[256*512];   // enc2 | pri2
__device__ float dWC[256*256];   // em|es|pm|ps
__device__ float dWD[384*256];   // dec1
__device__ float dWE[256*256];   // dec2
__device__ float dWF[256*64];    // dm|ds
__device__ float dWih[128*768];  // GRU input (cat rows 0:128)
__device__ float dWhh[256*768];  // GRU hidden (cat rows 128:384)
__device__ float dBA[512], dBB[512], dBC[256], dBD[256], dBE[256], dBF[64];
__device__ double dPart[NCTA*2];
__device__ unsigned int dCount;

__device__ __forceinline__ ull pk2(float a, float b) {
    ull r; asm("mov.b64 %0, {%1, %2};" : "=l"(r) : "f"(a), "f"(b)); return r;
}
__device__ __forceinline__ void upk2(ull v, float& a, float& b) {
    asm("mov.b64 {%0, %1}, %2;" : "=f"(a), "=f"(b) : "l"(v));
}
__device__ __forceinline__ void fma2(ull& d, ull a, ull b) {
    asm("fma.rn.f32x2 %0, %1, %2, %0;" : "+l"(d) : "l"(a), "l"(b));
}
__device__ __forceinline__ float sp(float x) { return (x > 15.f) ? x : log1pf(expf(x)); }
__device__ __forceinline__ float sigm(float x) { return 1.f / (1.f + expf(-x)); }

// Two output columns (n0, n1) over 8 batch rows starting at m0.
// Both columns read the SAME activation block (warp-broadcast LDS), so each
// 16B activation load feeds 8 fma2 (ratio 4:1).
template<int KLEN, int KC, bool RELU>
__device__ __forceinline__ void gemm2(const float* __restrict__ W, int NW,
                                      int n0, int n1, int kstart,
                                      float b0, float b1,
                                      const float* __restrict__ actS, int m0,
                                      float* __restrict__ o0,
                                      float* __restrict__ o1)
{
    ull acc0[4], acc1[4];
    {
        ull p0 = pk2(b0, b0), p1 = pk2(b1, b1);
        #pragma unroll
        for (int i = 0; i < 4; ++i) { acc0[i] = p0; acc1[i] = p1; }
    }
    const float* Wp = W + (size_t)kstart * NW;
    const float* Ap = actS + (size_t)kstart * MP + m0;
    #pragma unroll 1
    for (int k0 = 0; k0 < KLEN; k0 += KC) {
        float w0[KC], w1[KC];
        #pragma unroll
        for (int kk = 0; kk < KC; ++kk) {
            const float* wr = Wp + (size_t)(k0 + kk) * NW;
            w0[kk] = __ldg(wr + n0);
            w1[kk] = __ldg(wr + n1);
        }
        #pragma unroll
        for (int kk = 0; kk < KC; ++kk) {
            const float* ar = Ap + (k0 + kk) * MP;
            ulonglong2 a0 = *reinterpret_cast<const ulonglong2*>(ar);
            ulonglong2 a1 = *reinterpret_cast<const ulonglong2*>(ar + 4);
            ull w20 = pk2(w0[kk], w0[kk]);
            ull w21 = pk2(w1[kk], w1[kk]);
            fma2(acc0[0], w20, a0.x); fma2(acc0[1], w20, a0.y);
            fma2(acc0[2], w20, a1.x); fma2(acc0[3], w20, a1.y);
            fma2(acc1[0], w21, a0.x); fma2(acc1[1], w21, a0.y);
            fma2(acc1[2], w21, a1.x); fma2(acc1[3], w21, a1.y);
        }
    }
    #pragma unroll
    for (int i = 0; i < 4; ++i) {
        float lo, hi; upk2(acc0[i], lo, hi);
        if (RELU) { lo = fmaxf(lo, 0.f); hi = fmaxf(hi, 0.f); }
        *reinterpret_cast<float2*>(o0 + m0 + 2 * i) = make_float2(lo, hi);
    }
    #pragma unroll
    for (int i = 0; i < 4; ++i) {
        float lo, hi; upk2(acc1[i], lo, hi);
        if (RELU) { lo = fmaxf(lo, 0.f); hi = fmaxf(hi, 0.f); }
        *reinterpret_cast<float2*>(o1 + m0 + 2 * i) = make_float2(lo, hi);
    }
}

// dst[n][0:16] += src[n][0:16] (optional relu), n < N
template<bool RELU>
__device__ __forceinline__ void combine(float* __restrict__ dst,
                                        const float* __restrict__ src,
                                        int N, int tid)
{
    for (int i = tid; i < N * 8; i += NTHR) {
        int n = i >> 3, mp = (i & 7) * 2;
        float2 d = *reinterpret_cast<float2*>(dst + n * MP + mp);
        float2 s = *reinterpret_cast<const float2*>(src + n * MP + mp);
        d.x += s.x; d.y += s.y;
        if (RELU) { d.x = fmaxf(d.x, 0.f); d.y = fmaxf(d.y, 0.f); }
        *reinterpret_cast<float2*>(dst + n * MP + mp) = d;
    }
}

#define TOTAL_PREP 870208

__global__ void vrnn_prep(
    const float* __restrict__ enc_w1, const float* __restrict__ enc_b1,
    const float* __restrict__ enc_w2, const float* __restrict__ enc_b2,
    const float* __restrict__ enc_mw, const float* __restrict__ enc_mb,
    const float* __restrict__ enc_sw, const float* __restrict__ enc_sb,
    const float* __restrict__ pri_w1, const float* __restrict__ pri_b1,
    const float* __restrict__ pri_w2, const float* __restrict__ pri_b2,
    const float* __restrict__ pri_mw, const float* __restrict__ pri_mb,
    const float* __restrict__ pri_sw, const float* __restrict__ pri_sb,
    const float* __restrict__ dec_w1, const float* __restrict__ dec_b1,
    const float* __restrict__ dec_w2, const float* __restrict__ dec_b2,
    const float* __restrict__ dec_mw, const float* __restrict__ dec_mb,
    const float* __restrict__ dec_sw, const float* __restrict__ dec_sb,
    const float* __restrict__ wih,    const float* __restrict__ whh)
{
    int j = blockIdx.x * blockDim.x + threadIdx.x;
    if (j == 0) dCount = 0;
    if (j >= TOTAL_PREP) return;

    if (j < 384*512) {                 // WA: enc1(n<256) | pri1
        int k = j / 512, n = j % 512;
        float v = 0.f;
        if (n < 256) {                 // enc in [x,y,h]
            if (k < 64)        v = enc_w1[n*320 + k];
            else if (k >= 128) v = enc_w1[n*320 + k - 64];
        } else {                       // pri in [y,h]
            int q = n - 256;
            if (k >= 32 && k < 64) v = pri_w1[q*288 + k - 32];
            else if (k >= 128)     v = pri_w1[q*288 + k - 96];
        }
        dWA[j] = v; return;
    }
    j -= 384*512;
    if (j < 256*512) {
        int k = j / 512, n = j % 512;
        dWB[j] = (n < 256) ? enc_w2[n*256 + k] : pri_w2[(n-256)*256 + k];
        return;
    }
    j -= 256*512;
    if (j < 256*256) {
        int k = j / 256, n = j % 256;
        float v;
        if      (n < 64)  v = enc_mw[n*256 + k];
        else if (n < 128) v = enc_sw[(n-64)*256 + k];
        else if (n < 192) v = pri_mw[(n-128)*256 + k];
        else              v = pri_sw[(n-192)*256 + k];
        dWC[j] = v; return;
    }
    j -= 256*256;
    if (j < 384*256) {                 // dec in [y,z,h]: c = k-32 for k>=32
        int k = j / 256, n = j % 256;
        dWD[j] = (k >= 32) ? dec_w1[n*352 + k - 32] : 0.f;
        return;
    }
    j -= 384*256;
    if (j < 256*256) {
        int k = j / 256, n = j % 256;
        dWE[j] = dec_w2[n*256 + k]; return;
    }
    j -= 256*256;
    if (j < 256*64) {
        int k = j / 64, n = j % 64;
        dWF[j] = (n < 32) ? dec_mw[n*256 + k] : dec_sw[(n-32)*256 + k];
        return;
    }
    j -= 256*64;
    if (j < 128*768) {                 // GRU in [x,z]
        int k = j / 768, n = j % 768;
        float v = 0.f;
        if (k < 32)       v = wih[n*96 + k];
        else if (k >= 64) v = wih[n*96 + k - 32];
        dWih[j] = v; return;
    }
    j -= 128*768;
    if (j < 256*768) {
        int k = j / 768, n = j % 768;
        dWhh[j] = whh[n*256 + k]; return;
    }
    j -= 256*768;
    if (j < 512) { dBA[j] = (j < 256) ? enc_b1[j] : pri_b1[j-256]; return; }
    j -= 512;
    if (j < 512) { dBB[j] = (j < 256) ? enc_b2[j] : pri_b2[j-256]; return; }
    j -= 512;
    if (j < 256) {
        dBC[j] = (j < 64) ? enc_mb[j] : (j < 128) ? enc_sb[j-64]
               : (j < 192) ? pri_mb[j-128] : pri_sb[j-192];
        return;
    }
    j -= 256;
    if (j < 256) { dBD[j] = dec_b1[j]; return; }
    j -= 256;
    if (j < 256) { dBE[j] = dec_b2[j]; return; }
    j -= 256;
    dBF[j] = (j < 32) ? dec_mb[j] : dec_sb[j-32];
}

__global__ void __launch_bounds__(NTHR, 1)
vrnn_main(const float* __restrict__ states, const float* __restrict__ eps,
          const float* __restrict__ gbih,   const float* __restrict__ gbhh,
          float* __restrict__ out)
{
    extern __shared__ float sm[];
    float* CAT = sm;              // [384][MP]
    float* L1  = sm + 7680;       // [512][MP]
    float* L2  = sm + 17920;      // [512][MP]
    float* HB  = sm + 28160;      // [256][MP]

    const int tid  = threadIdx.x;
    const int row0 = blockIdx.x * MTILE;

    for (int i = tid; i < 7680; i += NTHR) CAT[i] = 0.f;  // zero z & h
    __syncthreads();

    // hoisted GRU biases (thread-role constants)
    const int gn = tid & 255;
    const float g_br = gbih[gn] + gbhh[gn];
    const float g_bz = gbih[256 + gn] + gbhh[256 + gn];
    const float g_bi = gbih[512 + gn];
    const float g_bh = gbhh[512 + gn];

    double klacc = 0.0, nllacc = 0.0;

    for (int t = 0; t < TSTEPS; ++t) {
        {   // load x=states[t+1], y=states[t], transposed to [k][m]
            const float* yb = states + ((size_t)t       * BATCH + row0) * 32;
            const float* xb = states + ((size_t)(t + 1) * BATCH + row0) * 32;
            int r = tid >> 5, c = tid & 31;
            CAT[c * MP + r]        = xb[r * 32 + c];
            CAT[(32 + c) * MP + r] = yb[r * 32 + c];
        }
        __syncthreads();

        // A: enc1|pri1  N=512 K=384 — cols (p, p+256), m-split, direct epilogue
        {
            int p = tid & 255, m0 = (tid >> 8) * 8;
            gemm2<384, 8, true>(dWA, 512, p, p + 256, 0, dBA[p], dBA[p + 256],
                                CAT, m0, L1 + p * MP, L1 + (p + 256) * MP);
        }
        __syncthreads();

        // B: enc2|pri2  N=512 K=256 — cols (n, n+128) within enc/pri half
        {
            int pp = tid & 255, m0 = (tid >> 8) * 8;
            int n0 = (pp < 128) ? pp : pp + 128;
            const float* act = L1 + ((pp < 128) ? 0 : 256 * MP);
            gemm2<256, 8, true>(dWB, 512, n0, n0 + 128, 0, dBB[n0], dBB[n0 + 128],
                                act, m0, L2 + n0 * MP, L2 + (n0 + 128) * MP);
        }
        __syncthreads();

        // C: heads em|es|pm|ps  N=256 K=256 — cols (q,q+64) in-half, k-split x2
        {
            int q = tid & 127, m0 = ((tid >> 7) & 1) * 8, kt = tid >> 8;
            int n0 = (q < 64) ? q : q + 64;
            const float* act = L2 + ((q < 64) ? 0 : 256 * MP);
            float* ob = kt ? L1 : HB;
            gemm2<128, 8, false>(dWC, 256, n0, n0 + 64, kt * 128,
                                 kt ? 0.f : dBC[n0], kt ? 0.f : dBC[n0 + 64],
                                 act, m0, ob + n0 * MP, ob + (n0 + 64) * MP);
        }
        __syncthreads();
        combine<false>(HB, L1, 256, tid);
        __syncthreads();

        {   // z = em + softplus(es)*eps; KL
            int n = tid & 63, mg = (tid >> 6) * 2;
            const float* eb = eps + ((size_t)t * BATCH + row0) * 64;
            float kls = 0.f;
            #pragma unroll
            for (int jj = 0; jj < 2; ++jj) {
                int m = mg + jj;
                float em = HB[n * MP + m];
                float es = sp(HB[(64  + n) * MP + m]);
                float pm = HB[(128 + n) * MP + m];
                float ps = sp(HB[(192 + n) * MP + m]);
                float e  = eb[m * 64 + n];
                CAT[(64 + n) * MP + m] = fmaf(es, e, em);
                float d = em - pm;
                kls += 2.f * (logf(ps) - logf(es)) + (es * es + d * d) / (ps * ps) - 1.f;
            }
            klacc += 0.5 * (double)kls;
        }
        __syncthreads();

        // D: dec1  N=256 K=384 — cols (q,q+128), k-split x2, partials in L1
        {
            int q = tid & 127, m0 = ((tid >> 7) & 1) * 8, kt = tid >> 8;
            float* ob = L1 + kt * 256 * MP;
            gemm2<192, 8, false>(dWD, 256, q, q + 128, kt * 192,
                                 kt ? 0.f : dBD[q], kt ? 0.f : dBD[q + 128],
                                 CAT, m0, ob + q * MP, ob + (q + 128) * MP);
        }
        __syncthreads();
        combine<true>(L1, L1 + 256 * MP, 256, tid);
        __syncthreads();

        // E: dec2  N=256 K=256 — cols (q,q+128), k-split x2, partials in L2
        {
            int q = tid & 127, m0 = ((tid >> 7) & 1) * 8, kt = tid >> 8;
            float* ob = L2 + kt * 256 * MP;
            gemm2<128, 8, false>(dWE, 256, q, q + 128, kt * 128,
                                 kt ? 0.f : dBE[q], kt ? 0.f : dBE[q + 128],
                                 L1, m0, ob + q * MP, ob + (q + 128) * MP);
        }
        __syncthreads();
        combine<true>(L2, L2 + 256 * MP, 256, tid);
        __syncthreads();

        // F: dm|ds  N=64 K=256 — cols (f,f+32), k-split x8, partials in L1
        {
            int f = tid & 31, m0 = ((tid >> 5) & 1) * 8, kt = tid >> 6;
            float* ob = L1 + kt * 64 * MP;
            gemm2<32, 8, false>(dWF, 64, f, f + 32, kt * 32,
                                kt ? 0.f : dBF[f], kt ? 0.f : dBF[f + 32],
                                L2, m0, ob + f * MP, ob + (f + 32) * MP);
        }
        __syncthreads();
        {   // F combine 8-way -> HB (512 items, one per thread)
            int n = tid >> 3, mp = (tid & 7) * 2;
            float2 s = *reinterpret_cast<float2*>(L1 + n * MP + mp);
            #pragma unroll
            for (int b = 1; b < 8; ++b) {
                float2 p = *reinterpret_cast<float2*>(L1 + b * 64 * MP + n * MP + mp);
                s.x += p.x; s.y += p.y;
            }
            *reinterpret_cast<float2*>(HB + n * MP + mp) = s;
        }
        __syncthreads();

        {   // NLL
            int n = tid & 31, m = tid >> 5;
            float dm = HB[n * MP + m];
            float ds = sp(HB[(32 + n) * MP + m]);
            float dd = CAT[n * MP + m] - dm;
            nllacc += (double)(logf(ds) + dd * dd / (2.f * ds * ds)
                               + 0.91893853320467274f);
        }

        {   // fused GRU: gi + gh + gates; thread = (n 0..255, m-half)
            const int n = gn;
            const int m0 = (tid >> 8) * 8;
            ull ar[4], az[4], ai[4], ah[4];
            {
                ull r0 = pk2(g_br, g_br), z0 = pk2(g_bz, g_bz);
                ull i0 = pk2(g_bi, g_bi), h0 = pk2(g_bh, g_bh);
                #pragma unroll
                for (int i = 0; i < 4; ++i) { ar[i]=r0; az[i]=z0; ai[i]=i0; ah[i]=h0; }
            }
            #pragma unroll 1
            for (int k0 = 0; k0 < 128; k0 += 8) {        // input part, cat[0:128)
                float wr[8], wz[8], wn[8];
                #pragma unroll
                for (int kk = 0; kk < 8; ++kk) {
                    const float* wp = dWih + (size_t)(k0 + kk) * 768;
                    wr[kk] = __ldg(wp + n);
                    wz[kk] = __ldg(wp + 256 + n);
                    wn[kk] = __ldg(wp + 512 + n);
                }
                #pragma unroll
                for (int kk = 0; kk < 8; ++kk) {
                    const float* a = CAT + (k0 + kk) * MP + m0;
                    ulonglong2 a0 = *reinterpret_cast<const ulonglong2*>(a);
                    ulonglong2 a1 = *reinterpret_cast<const ulonglong2*>(a + 4);
                    ull wr2 = pk2(wr[kk], wr[kk]);
                    ull wz2 = pk2(wz[kk], wz[kk]);
                    ull wn2 = pk2(wn[kk], wn[kk]);
                    fma2(ar[0],wr2,a0.x); fma2(ar[1],wr2,a0.y);
                    fma2(ar[2],wr2,a1.x); fma2(ar[3],wr2,a1.y);
                    fma2(az[0],wz2,a0.x); fma2(az[1],wz2,a0.y);
                    fma2(az[2],wz2,a1.x); fma2(az[3],wz2,a1.y);
                    fma2(ai[0],wn2,a0.x); fma2(ai[1],wn2,a0.y);
                    fma2(ai[2],wn2,a1.x); fma2(ai[3],wn2,a1.y);
                }
            }
            #pragma unroll 1
            for (int k0 = 0; k0 < 256; k0 += 8) {        // hidden part, cat[128:384)
                float wr[8], wz[8], wn[8];
                #pragma unroll
                for (int kk = 0; kk < 8; ++kk) {
                    const float* wp = dWhh + (size_t)(k0 + kk) * 768;
                    wr[kk] = __ldg(wp + n);
                    wz[kk] = __ldg(wp + 256 + n);
                    wn[kk] = __ldg(wp + 512 + n);
                }
                #pragma unroll
                for (int kk = 0; kk < 8; ++kk) {
                    const float* a = CAT + (128 + k0 + kk) * MP + m0;
                    ulonglong2 a0 = *reinterpret_cast<const ulonglong2*>(a);
                    ulonglong2 a1 = *reinterpret_cast<const ulonglong2*>(a + 4);
                    ull wr2 = pk2(wr[kk], wr[kk]);
                    ull wz2 = pk2(wz[kk], wz[kk]);
                    ull wn2 = pk2(wn[kk], wn[kk]);
                    fma2(ar[0],wr2,a0.x); fma2(ar[1],wr2,a0.y);
                    fma2(ar[2],wr2,a1.x); fma2(ar[3],wr2,a1.y);
                    fma2(az[0],wz2,a0.x); fma2(az[1],wz2,a0.y);
                    fma2(az[2],wz2,a1.x); fma2(az[3],wz2,a1.y);
                    fma2(ah[0],wn2,a0.x); fma2(ah[1],wn2,a0.y);
                    fma2(ah[2],wn2,a1.x); fma2(ah[3],wn2,a1.y);
                }
            }
            float hold[8];
            #pragma unroll
            for (int m = 0; m < 8; ++m) hold[m] = CAT[(128 + n) * MP + m0 + m];
            __syncthreads();   // all reads of old h / x / z done
            #pragma unroll
            for (int i = 0; i < 4; ++i) {
                float rA, rB, uA, uB, iA, iB, hA, hB;
                upk2(ar[i], rA, rB); upk2(az[i], uA, uB);
                upk2(ai[i], iA, iB); upk2(ah[i], hA, hB);
                rA = sigm(rA); rB = sigm(rB);
                uA = sigm(uA); uB = sigm(uB);
                float nA = tanhf(iA + rA * hA);
                float nB = tanhf(iB + rB * hB);
                CAT[(128 + n) * MP + m0 + 2*i]     = (1.f - uA) * nA + uA * hold[2*i];
                CAT[(128 + n) * MP + m0 + 2*i + 1] = (1.f - uB) * nB + uB * hold[2*i + 1];
            }
            __syncthreads();
        }
    }

    // deterministic block reduction of losses
    double* red = reinterpret_cast<double*>(sm);
    red[tid] = klacc; red[NTHR + tid] = nllacc;
    __syncthreads();
    for (int s = NTHR / 2; s > 0; s >>= 1) {
        if (tid < s) { red[tid] += red[tid + s]; red[NTHR + tid] += red[NTHR + tid + s]; }
        __syncthreads();
    }
    if (tid == 0) {
        dPart[blockIdx.x * 2]     = red[0];
        dPart[blockIdx.x * 2 + 1] = red[NTHR];
        __threadfence();
        atomicAdd(&dCount, 1u);
        if (blockIdx.x == 0) {   // grid=128 <= SM count, 1 CTA/SM: all resident
            while (atomicAdd(&dCount, 0u) < (unsigned)gridDim.x) { __nanosleep(200); }
            double kl = 0.0, nl = 0.0;
            for (int i = 0; i < NCTA; ++i) { kl += dPart[2*i]; nl += dPart[2*i+1]; }
            out[0] = (float)kl; out[1] = (float)nl;
        }
    }
}

extern "C" void kernel_launch(void* const* d_in, const int* in_sizes, int n_in,
                              void* d_out, int out_size) {
    const float* states = (const float*)d_in[0];
    const float* eps    = (const float*)d_in[1];
    const float *enc_w1 = (const float*)d_in[2],  *enc_b1 = (const float*)d_in[3];
    const float *enc_w2 = (const float*)d_in[4],  *enc_b2 = (const float*)d_in[5];
    const float *enc_mw = (const float*)d_in[6],  *enc_mb = (const float*)d_in[7];
    const float *enc_sw = (const float*)d_in[8],  *enc_sb = (const float*)d_in[9];
    const float *pri_w1 = (const float*)d_in[10], *pri_b1 = (const float*)d_in[11];
    const float *pri_w2 = (const float*)d_in[12], *pri_b2 = (const float*)d_in[13];
    const float *pri_mw = (const float*)d_in[14], *pri_mb = (const float*)d_in[15];
    const float *pri_sw = (const float*)d_in[16], *pri_sb = (const float*)d_in[17];
    const float *dec_w1 = (const float*)d_in[18], *dec_b1 = (const float*)d_in[19];
    const float *dec_w2 = (const float*)d_in[20], *dec_b2 = (const float*)d_in[21];
    const float *dec_mw = (const float*)d_in[22], *dec_mb = (const float*)d_in[23];
    const float *dec_sw = (const float*)d_in[24], *dec_sb = (const float*)d_in[25];
    const float *gwih   = (const float*)d_in[26], *gwhh   = (const float*)d_in[27];
    const float *gbih   = (const float*)d_in[28], *gbhh   = (const float*)d_in[29];
    float* out = (float*)d_out;

    static bool attrSet = false;
    if (!attrSet) {
        cudaFuncSetAttribute(vrnn_main, cudaFuncAttributeMaxDynamicSharedMemorySize,
                             33280 * (int)sizeof(float));
        attrSet = true;
    }

    vrnn_prep<<<(TOTAL_PREP + 255) / 256, 256>>>(
        enc_w1, enc_b1, enc_w2, enc_b2, enc_mw, enc_mb, enc_sw, enc_sb,
        pri_w1, pri_b1, pri_w2, pri_b2, pri_mw, pri_mb, pri_sw, pri_sb,
        dec_w1, dec_b1, dec_w2, dec_b2, dec_mw, dec_mb, dec_sw, dec_sb,
        gwih, gwhh);
    vrnn_main<<<NCTA, NTHR, 33280 * sizeof(float)>>>(states, eps, gbih, gbhh, out);
}

// round 14
// speedup vs baseline: 1.1104x; 1.1098x over previous
#include <cuda_runtime.h>
#include <math.h>
#include <stdint.h>

#define MP      20
#define TSTEPS  199
#define BATCH   2048
#define MTILE   16
#define NCTA    128
#define NTHR    512

typedef unsigned long long ull;

// cat k-axis (NEW order): x 0:32 | y 32:64 | h 64:320 | z 320:384
__device__ float dWA[320*512];   // enc1 (k 0:320) | pri1 (k 32:320)
__device__ float dWB[256*512];   // enc2 | pri2
__device__ float dWC[256*256];   // em|es|pm|ps
__device__ float dWD[384*256];   // dec1 (k 32:384 used)
__device__ float dWE[256*256];   // dec2
__device__ float dWF[256*64];    // dm|ds
__device__ float dWih[96*768];   // GRU input, compact rows: x 0:32 | z 32:96
__device__ float dWhh[256*768];  // GRU hidden (h)
__device__ float dBA[512], dBB[512], dBC[256], dBD[256], dBE[256], dBF[64];
__device__ double dPart[NCTA*2];
__device__ unsigned int dCount;

__device__ __forceinline__ ull pk2(float a, float b) {
    ull r; asm("mov.b64 %0, {%1, %2};" : "=l"(r) : "f"(a), "f"(b)); return r;
}
__device__ __forceinline__ void upk2(ull v, float& a, float& b) {
    asm("mov.b64 {%0, %1}, %2;" : "=f"(a), "=f"(b) : "l"(v));
}
__device__ __forceinline__ void fma2(ull& d, ull a, ull b) {
    asm("fma.rn.f32x2 %0, %1, %2, %0;" : "+l"(d) : "l"(a), "l"(b));
}
__device__ __forceinline__ float sp(float x) { return (x > 15.f) ? x : log1pf(expf(x)); }
__device__ __forceinline__ float sigm(float x) { return 1.f / (1.f + expf(-x)); }

#define FMA8(A, w, q0, q1, q2, q3) \
    fma2(A[0], w, q0.x); fma2(A[1], w, q0.y); \
    fma2(A[2], w, q1.x); fma2(A[3], w, q1.y); \
    fma2(A[4], w, q2.x); fma2(A[5], w, q2.y); \
    fma2(A[6], w, q3.x); fma2(A[7], w, q3.y);

// Two ADJACENT output columns (n0, n0+1) over ALL 16 batch rows.
// Weight fetch = one coalesced float2 LDG per k per thread (multiplicity 1).
template<int KLEN, bool RELU>
__device__ __forceinline__ void gemm2(const float* __restrict__ W, int NW,
                                      int n0, int kstart,
                                      float b0, float b1,
                                      const float* __restrict__ actS,
                                      float* __restrict__ o0,
                                      float* __restrict__ o1)
{
    ull A0[8], A1[8];
    {
        ull p0 = pk2(b0, b0), p1 = pk2(b1, b1);
        #pragma unroll
        for (int i = 0; i < 8; ++i) { A0[i] = p0; A1[i] = p1; }
    }
    const float* Wp = W + (size_t)kstart * NW + n0;
    const float* Ap = actS + (size_t)kstart * MP;
    #pragma unroll 1
    for (int k0 = 0; k0 < KLEN; k0 += 8) {
        float2 w[8];
        #pragma unroll
        for (int kk = 0; kk < 8; ++kk)
            w[kk] = __ldg(reinterpret_cast<const float2*>(Wp + (size_t)(k0 + kk) * NW));
        #pragma unroll
        for (int kk = 0; kk < 8; ++kk) {
            const float* ar = Ap + (k0 + kk) * MP;
            ulonglong2 q0 = *reinterpret_cast<const ulonglong2*>(ar);
            ulonglong2 q1 = *reinterpret_cast<const ulonglong2*>(ar + 4);
            ulonglong2 q2 = *reinterpret_cast<const ulonglong2*>(ar + 8);
            ulonglong2 q3 = *reinterpret_cast<const ulonglong2*>(ar + 12);
            ull w0 = pk2(w[kk].x, w[kk].x);
            ull w1 = pk2(w[kk].y, w[kk].y);
            FMA8(A0, w0, q0, q1, q2, q3);
            FMA8(A1, w1, q0, q1, q2, q3);
        }
    }
    #pragma unroll
    for (int i = 0; i < 8; ++i) {
        float lo, hi; upk2(A0[i], lo, hi);
        if (RELU) { lo = fmaxf(lo, 0.f); hi = fmaxf(hi, 0.f); }
        *reinterpret_cast<float2*>(o0 + 2 * i) = make_float2(lo, hi);
    }
    #pragma unroll
    for (int i = 0; i < 8; ++i) {
        float lo, hi; upk2(A1[i], lo, hi);
        if (RELU) { lo = fmaxf(lo, 0.f); hi = fmaxf(hi, 0.f); }
        *reinterpret_cast<float2*>(o1 + 2 * i) = make_float2(lo, hi);
    }
}

// GRU accumulate helpers: chains over 16 rows, weight stride 768.
template<int KLEN>
__device__ __forceinline__ void acc2(const float* __restrict__ W, int o0, int o1,
                                     const float* __restrict__ Ap, ull* A0, ull* A1)
{
    #pragma unroll 1
    for (int k0 = 0; k0 < KLEN; k0 += 8) {
        float wa[8], wb[8];
        #pragma unroll
        for (int kk = 0; kk < 8; ++kk) {
            const float* wr = W + (size_t)(k0 + kk) * 768;
            wa[kk] = __ldg(wr + o0);
            wb[kk] = __ldg(wr + o1);
        }
        #pragma unroll
        for (int kk = 0; kk < 8; ++kk) {
            const float* ar = Ap + (k0 + kk) * MP;
            ulonglong2 q0 = *reinterpret_cast<const ulonglong2*>(ar);
            ulonglong2 q1 = *reinterpret_cast<const ulonglong2*>(ar + 4);
            ulonglong2 q2 = *reinterpret_cast<const ulonglong2*>(ar + 8);
            ulonglong2 q3 = *reinterpret_cast<const ulonglong2*>(ar + 12);
            ull w0 = pk2(wa[kk], wa[kk]);
            ull w1 = pk2(wb[kk], wb[kk]);
            FMA8(A0, w0, q0, q1, q2, q3);
            FMA8(A1, w1, q0, q1, q2, q3);
        }
    }
}
template<int KLEN>
__device__ __forceinline__ void acc1(const float* __restrict__ W, int o0,
                                     const float* __restrict__ Ap, ull* A0)
{
    #pragma unroll 1
    for (int k0 = 0; k0 < KLEN; k0 += 8) {
        float wa[8];
        #pragma unroll
        for (int kk = 0; kk < 8; ++kk)
            wa[kk] = __ldg(W + (size_t)(k0 + kk) * 768 + o0);
        #pragma unroll
        for (int kk = 0; kk < 8; ++kk) {
            const float* ar = Ap + (k0 + kk) * MP;
            ulonglong2 q0 = *reinterpret_cast<const ulonglong2*>(ar);
            ulonglong2 q1 = *reinterpret_cast<const ulonglong2*>(ar + 4);
            ulonglong2 q2 = *reinterpret_cast<const ulonglong2*>(ar + 8);
            ulonglong2 q3 = *reinterpret_cast<const ulonglong2*>(ar + 12);
            ull w0 = pk2(wa[kk], wa[kk]);
            FMA8(A0, w0, q0, q1, q2, q3);
        }
    }
}

#define TOTAL_PREP 812864

__global__ void vrnn_prep(
    const float* __restrict__ enc_w1, const float* __restrict__ enc_b1,
    const float* __restrict__ enc_w2, const float* __restrict__ enc_b2,
    const float* __restrict__ enc_mw, const float* __restrict__ enc_mb,
    const float* __restrict__ enc_sw, const float* __restrict__ enc_sb,
    const float* __restrict__ pri_w1, const float* __restrict__ pri_b1,
    const float* __restrict__ pri_w2, const float* __restrict__ pri_b2,
    const float* __restrict__ pri_mw, const float* __restrict__ pri_mb,
    const float* __restrict__ pri_sw, const float* __restrict__ pri_sb,
    const float* __restrict__ dec_w1, const float* __restrict__ dec_b1,
    const float* __restrict__ dec_w2, const float* __restrict__ dec_b2,
    const float* __restrict__ dec_mw, const float* __restrict__ dec_mb,
    const float* __restrict__ dec_sw, const float* __restrict__ dec_sb,
    const float* __restrict__ wih,    const float* __restrict__ whh)
{
    int j = blockIdx.x * blockDim.x + threadIdx.x;
    if (j == 0) dCount = 0;
    if (j >= TOTAL_PREP) return;

    if (j < 320*512) {                 // WA: enc1 | pri1; cat rows 0:320
        int k = j / 512, n = j % 512;
        float v;
        if (n < 256) v = enc_w1[n*320 + k];             // enc in [x,y,h] == cat
        else v = (k >= 32) ? pri_w1[(n-256)*288 + k - 32] : 0.f;  // pri in [y,h]
        dWA[j] = v; return;
    }
    j -= 320*512;
    if (j < 256*512) {
        int k = j / 512, n = j % 512;
        dWB[j] = (n < 256) ? enc_w2[n*256 + k] : pri_w2[(n-256)*256 + k];
        return;
    }
    j -= 256*512;
    if (j < 256*256) {
        int k = j / 256, n = j % 256;
        float v;
        if      (n < 64)  v = enc_mw[n*256 + k];
        else if (n < 128) v = enc_sw[(n-64)*256 + k];
        else if (n < 192) v = pri_mw[(n-128)*256 + k];
        else              v = pri_sw[(n-192)*256 + k];
        dWC[j] = v; return;
    }
    j -= 256*256;
    if (j < 384*256) {                 // dec in [y,z,h]; cat [x|y|h|z]
        int k = j / 256, n = j % 256;
        float v = 0.f;
        if      (k >= 320)  v = dec_w1[n*352 + k - 288]; // z: dec cols 32:96
        else if (k >= 64)   v = dec_w1[n*352 + k + 32];  // h: dec cols 96:352
        else if (k >= 32)   v = dec_w1[n*352 + k - 32];  // y: dec cols 0:32
        dWD[j] = v; return;
    }
    j -= 384*256;
    if (j < 256*256) {
        int k = j / 256, n = j % 256;
        dWE[j] = dec_w2[n*256 + k]; return;
    }
    j -= 256*256;
    if (j < 256*64) {
        int k = j / 64, n = j % 64;
        dWF[j] = (n < 32) ? dec_mw[n*256 + k] : dec_sw[(n-32)*256 + k];
        return;
    }
    j -= 256*64;
    if (j < 96*768) {                  // GRU in [x,z] compact == wih col order
        int k = j / 768, n = j % 768;
        dWih[j] = wih[n*96 + k]; return;
    }
    j -= 96*768;
    if (j < 256*768) {
        int k = j / 768, n = j % 768;
        dWhh[j] = whh[n*256 + k]; return;
    }
    j -= 256*768;
    if (j < 512) { dBA[j] = (j < 256) ? enc_b1[j] : pri_b1[j-256]; return; }
    j -= 512;
    if (j < 512) { dBB[j] = (j < 256) ? enc_b2[j] : pri_b2[j-256]; return; }
    j -= 512;
    if (j < 256) {
        dBC[j] = (j < 64) ? enc_mb[j] : (j < 128) ? enc_sb[j-64]
               : (j < 192) ? pri_mb[j-128] : pri_sb[j-192];
        return;
    }
    j -= 256;
    if (j < 256) { dBD[j] = dec_b1[j]; return; }
    j -= 256;
    if (j < 256) { dBE[j] = dec_b2[j]; return; }
    j -= 256;
    dBF[j] = (j < 32) ? dec_mb[j] : dec_sb[j-32];
}

__global__ void __launch_bounds__(NTHR, 1)
vrnn_main(const float* __restrict__ states, const float* __restrict__ eps,
          const float* __restrict__ gbih,   const float* __restrict__ gbhh,
          float* __restrict__ out)
{
    extern __shared__ float sm[];
    float* CAT = sm;              // [384][MP]   7680
    float* L1  = sm + 7680;       // [512][MP]  10240
    float* L2  = sm + 17920;      // [512][MP]  10240
    float* L3  = sm + 28160;      // [512][MP]  10240
    float* HB  = sm + 38400;      // [256][MP]   5120   (total 43520 f = 170KB)

    const int tid  = threadIdx.x;
    const int row0 = blockIdx.x * MTILE;

    for (int i = tid; i < 7680; i += NTHR) CAT[i] = 0.f;  // zero h & z
    __syncthreads();

    const int gn = tid & 255;
    const float g_br = gbih[gn] + gbhh[gn];
    const float g_bz = gbih[256 + gn] + gbhh[256 + gn];
    const float g_bi = gbih[512 + gn];
    const float g_bh = gbhh[512 + gn];

    double klacc = 0.0, nllacc = 0.0;

    for (int t = 0; t < TSTEPS; ++t) {
        {   // load x=states[t+1] (rows 0:32), y=states[t] (rows 32:64)
            const float* yb = states + ((size_t)t       * BATCH + row0) * 32;
            const float* xb = states + ((size_t)(t + 1) * BATCH + row0) * 32;
            int r = tid >> 5, c = tid & 31;
            CAT[c * MP + r]        = xb[r * 32 + c];
            CAT[(32 + c) * MP + r] = yb[r * 32 + c];
        }
        __syncthreads();

        // A: enc1|pri1 N=512; cols (2q,2q+1); k-split x2; partials L1/L3
        {
            int q = tid & 255, kt = tid >> 8, n0 = 2 * q;
            float* ob = kt ? L3 : L1;
            float b0 = kt ? 0.f : dBA[n0], b1 = kt ? 0.f : dBA[n0 + 1];
            if (q < 128)
                gemm2<160, false>(dWA, 512, n0, kt * 160, b0, b1, CAT,
                                  ob + n0 * MP, ob + (n0 + 1) * MP);
            else
                gemm2<144, false>(dWA, 512, n0, 32 + kt * 144, b0, b1, CAT,
                                  ob + n0 * MP, ob + (n0 + 1) * MP);
        }
        __syncthreads();
        for (int i = tid; i < 512 * 8; i += NTHR) {   // L1 = relu(L1+L3)
            int n = i >> 3, mp = (i & 7) * 2;
            float2 d = *reinterpret_cast<float2*>(L1 + n * MP + mp);
            float2 s = *reinterpret_cast<float2*>(L3 + n * MP + mp);
            d.x = fmaxf(d.x + s.x, 0.f); d.y = fmaxf(d.y + s.y, 0.f);
            *reinterpret_cast<float2*>(L1 + n * MP + mp) = d;
        }
        __syncthreads();

        // B: enc2|pri2 N=512 K=256; k-split x2; partials L2/L3
        {
            int q = tid & 255, kt = tid >> 8, n0 = 2 * q;
            const float* act = L1 + ((q < 128) ? 0 : 256 * MP);
            float* ob = kt ? L3 : L2;
            gemm2<128, false>(dWB, 512, n0, kt * 128,
                              kt ? 0.f : dBB[n0], kt ? 0.f : dBB[n0 + 1],
                              act, ob + n0 * MP, ob + (n0 + 1) * MP);
        }
        __syncthreads();
        for (int i = tid; i < 512 * 8; i += NTHR) {   // L2 = relu(L2+L3)
            int n = i >> 3, mp = (i & 7) * 2;
            float2 d = *reinterpret_cast<float2*>(L2 + n * MP + mp);
            float2 s = *reinterpret_cast<float2*>(L3 + n * MP + mp);
            d.x = fmaxf(d.x + s.x, 0.f); d.y = fmaxf(d.y + s.y, 0.f);
            *reinterpret_cast<float2*>(L2 + n * MP + mp) = d;
        }
        __syncthreads();

        // C: heads N=256 K=256; k-split x4; partials HB/L3a/L3b/L1a
        {
            int q = tid & 127, kt = tid >> 7, n0 = 2 * q;
            const float* act = L2 + ((q < 64) ? 0 : 256 * MP);
            float* ob = (kt == 0) ? HB : (kt == 1) ? L3
                      : (kt == 2) ? L3 + 256 * MP : L1;
            gemm2<64, false>(dWC, 256, n0, kt * 64,
                             kt ? 0.f : dBC[n0], kt ? 0.f : dBC[n0 + 1],
                             act, ob + n0 * MP, ob + (n0 + 1) * MP);
        }
        __syncthreads();
        for (int i = tid; i < 256 * 8; i += NTHR) {   // HB += L3a+L3b+L1a
            int n = i >> 3, mp = (i & 7) * 2;
            float2 d  = *reinterpret_cast<float2*>(HB + n * MP + mp);
            float2 s1 = *reinterpret_cast<float2*>(L3 + n * MP + mp);
            float2 s2 = *reinterpret_cast<float2*>(L3 + (256 + n) * MP + mp);
            float2 s3 = *reinterpret_cast<float2*>(L1 + n * MP + mp);
            d.x += s1.x + s2.x + s3.x; d.y += s1.y + s2.y + s3.y;
            *reinterpret_cast<float2*>(HB + n * MP + mp) = d;
        }
        __syncthreads();

        {   // z = em + softplus(es)*eps (z rows = 320+n); KL
            int n = tid & 63, mg = (tid >> 6) * 2;
            const float* eb = eps + ((size_t)t * BATCH + row0) * 64;
            float kls = 0.f;
            #pragma unroll
            for (int jj = 0; jj < 2; ++jj) {
                int m = mg + jj;
                float em = HB[n * MP + m];
                float es = sp(HB[(64  + n) * MP + m]);
                float pm = HB[(128 + n) * MP + m];
                float ps = sp(HB[(192 + n) * MP + m]);
                float e  = eb[m * 64 + n];
                CAT[(320 + n) * MP + m] = fmaf(es, e, em);
                float d = em - pm;
                kls += 2.f * (logf(ps) - logf(es)) + (es * es + d * d) / (ps * ps) - 1.f;
            }
            klacc += 0.5 * (double)kls;
        }
        __syncthreads();

        // D: dec1 N=256 K=352 (kstart 32); k-split x4; partials L1a/L1b/L3a/L3b
        {
            int q = tid & 127, kt = tid >> 7, n0 = 2 * q;
            float* ob = (kt == 0) ? L1 : (kt == 1) ? L1 + 256 * MP
                      : (kt == 2) ? L3 : L3 + 256 * MP;
            gemm2<88, false>(dWD, 256, n0, 32 + kt * 88,
                             kt ? 0.f : dBD[n0], kt ? 0.f : dBD[n0 + 1],
                             CAT, ob + n0 * MP, ob + (n0 + 1) * MP);
        }
        __syncthreads();
        for (int i = tid; i < 256 * 8; i += NTHR) {   // L1a = relu(sum of 4)
            int n = i >> 3, mp = (i & 7) * 2;
            float2 d  = *reinterpret_cast<float2*>(L1 + n * MP + mp);
            float2 s1 = *reinterpret_cast<float2*>(L1 + (256 + n) * MP + mp);
            float2 s2 = *reinterpret_cast<float2*>(L3 + n * MP + mp);
            float2 s3 = *reinterpret_cast<float2*>(L3 + (256 + n) * MP + mp);
            d.x = fmaxf(d.x + s1.x + s2.x + s3.x, 0.f);
            d.y = fmaxf(d.y + s1.y + s2.y + s3.y, 0.f);
            *reinterpret_cast<float2*>(L1 + n * MP + mp) = d;
        }
        __syncthreads();

        // E: dec2 N=256 K=256; k-split x4; partials L2a/L2b/L3a/L3b
        {
            int q = tid & 127, kt = tid >> 7, n0 = 2 * q;
            float* ob = (kt == 0) ? L2 : (kt == 1) ? L2 + 256 * MP
                      : (kt == 2) ? L3 : L3 + 256 * MP;
            gemm2<64, false>(dWE, 256, n0, kt * 64,
                             kt ? 0.f : dBE[n0], kt ? 0.f : dBE[n0 + 1],
                             L1, ob + n0 * MP, ob + (n0 + 1) * MP);
        }
        __syncthreads();
        for (int i = tid; i < 256 * 8; i += NTHR) {   // L2a = relu(sum of 4)
            int n = i >> 3, mp = (i & 7) * 2;
            float2 d  = *reinterpret_cast<float2*>(L2 + n * MP + mp);
            float2 s1 = *reinterpret_cast<float2*>(L2 + (256 + n) * MP + mp);
            float2 s2 = *reinterpret_cast<float2*>(L3 + n * MP + mp);
            float2 s3 = *reinterpret_cast<float2*>(L3 + (256 + n) * MP + mp);
            d.x = fmaxf(d.x + s1.x + s2.x + s3.x, 0.f);
            d.y = fmaxf(d.y + s1.y + s2.y + s3.y, 0.f);
            *reinterpret_cast<float2*>(L2 + n * MP + mp) = d;
        }
        __syncthreads();

        // F: dm|ds N=64 K=256; k-split x16; partials L3[0:8]/L1[0:8] blocks
        {
            int f = tid & 31, kt = tid >> 5, n0 = 2 * f;
            float* ob = (kt < 8) ? L3 + kt * 64 * MP : L1 + (kt - 8) * 64 * MP;
            gemm2<16, false>(dWF, 64, n0, kt * 16,
                             kt ? 0.f : dBF[n0], kt ? 0.f : dBF[n0 + 1],
                             L2, ob + n0 * MP, ob + (n0 + 1) * MP);
        }
        __syncthreads();
        {   // F combine 16-way -> HB (512 slots, one per thread)
            int n = tid >> 3, mp = (tid & 7) * 2;
            float2 s = *reinterpret_cast<float2*>(L3 + n * MP + mp);
            #pragma unroll
            for (int b = 1; b < 8; ++b) {
                float2 p = *reinterpret_cast<float2*>(L3 + b * 64 * MP + n * MP + mp);
                s.x += p.x; s.y += p.y;
            }
            #pragma unroll
            for (int b = 0; b < 8; ++b) {
                float2 p = *reinterpret_cast<float2*>(L1 + b * 64 * MP + n * MP + mp);
                s.x += p.x; s.y += p.y;
            }
            *reinterpret_cast<float2*>(HB + n * MP + mp) = s;
        }
        __syncthreads();

        {   // NLL
            int n = tid & 31, m = tid >> 5;
            float dm = HB[n * MP + m];
            float ds = sp(HB[(32 + n) * MP + m]);
            float dd = CAT[n * MP + m] - dm;
            nllacc += (double)(logf(ds) + dd * dd / (2.f * ds * ds)
                               + 0.91893853320467274f);
        }

        // GRU: g0 accumulates r,z gates; g1 accumulates n-gates (i over x,z; h over h)
        {
            const int n = gn, g = tid >> 8;
            if (g == 0) {
                ull ar[8], az[8];
                {
                    ull r0 = pk2(g_br, g_br), z0 = pk2(g_bz, g_bz);
                    #pragma unroll
                    for (int i = 0; i < 8; ++i) { ar[i] = r0; az[i] = z0; }
                }
                acc2<32> (dWih,            n, 256 + n, CAT,            ar, az); // x
                acc2<64> (dWih + 32 * 768, n, 256 + n, CAT + 320 * MP, ar, az); // z
                acc2<256>(dWhh,            n, 256 + n, CAT + 64 * MP,  ar, az); // h
                #pragma unroll
                for (int i = 0; i < 8; ++i) {
                    float rA, rB, uA, uB;
                    upk2(ar[i], rA, rB); upk2(az[i], uA, uB);
                    *reinterpret_cast<float2*>(L3 + n * MP + 2 * i)
                        = make_float2(sigm(rA), sigm(rB));
                    *reinterpret_cast<float2*>(L3 + (256 + n) * MP + 2 * i)
                        = make_float2(sigm(uA), sigm(uB));
                }
                __syncthreads();   // r,u visible
            } else {
                ull ai[8], ah[8];
                {
                    ull i0 = pk2(g_bi, g_bi), h0 = pk2(g_bh, g_bh);
                    #pragma unroll
                    for (int i = 0; i < 8; ++i) { ai[i] = i0; ah[i] = h0; }
                }
                acc1<32> (dWih,            512 + n, CAT,            ai);
                acc1<64> (dWih + 32 * 768, 512 + n, CAT + 320 * MP, ai);
                acc1<256>(dWhh,            512 + n, CAT + 64 * MP,  ah);
                __syncthreads();   // r,u visible
                #pragma unroll
                for (int i = 0; i < 8; ++i) {
                    float iA, iB, hA, hB;
                    upk2(ai[i], iA, iB); upk2(ah[i], hA, hB);
                    float2 r2 = *reinterpret_cast<float2*>(L3 + n * MP + 2 * i);
                    float2 u2 = *reinterpret_cast<float2*>(L3 + (256 + n) * MP + 2 * i);
                    float hoA = CAT[(64 + n) * MP + 2 * i];
                    float hoB = CAT[(64 + n) * MP + 2 * i + 1];
                    float nA = tanhf(iA + r2.x * hA);
                    float nB = tanhf(iB + r2.y * hB);
                    CAT[(64 + n) * MP + 2 * i]     = (1.f - u2.x) * nA + u2.x * hoA;
                    CAT[(64 + n) * MP + 2 * i + 1] = (1.f - u2.y) * nB + u2.y * hoB;
                }
            }
            __syncthreads();
        }
    }

    // deterministic block reduction of losses
    double* red = reinterpret_cast<double*>(sm);
    red[tid] = klacc; red[NTHR + tid] = nllacc;
    __syncthreads();
    for (int s = NTHR / 2; s > 0; s >>= 1) {
        if (tid < s) { red[tid] += red[tid + s]; red[NTHR + tid] += red[NTHR + tid + s]; }
        __syncthreads();
    }
    if (tid == 0) {
        dPart[blockIdx.x * 2]     = red[0];
        dPart[blockIdx.x * 2 + 1] = red[NTHR];
        __threadfence();
        atomicAdd(&dCount, 1u);
        if (blockIdx.x == 0) {   // all 128 CTAs resident (1/SM): spin is safe
            while (atomicAdd(&dCount, 0u) < (unsigned)gridDim.x) { __nanosleep(200); }
            double kl = 0.0, nl = 0.0;
            for (int i = 0; i < NCTA; ++i) { kl += dPart[2*i]; nl += dPart[2*i+1]; }
            out[0] = (float)kl; out[1] = (float)nl;
        }
    }
}

extern "C" void kernel_launch(void* const* d_in, const int* in_sizes, int n_in,
                              void* d_out, int out_size) {
    const float* states = (const float*)d_in[0];
    const float* eps    = (const float*)d_in[1];
    const float *enc_w1 = (const float*)d_in[2],  *enc_b1 = (const float*)d_in[3];
    const float *enc_w2 = (const float*)d_in[4],  *enc_b2 = (const float*)d_in[5];
    const float *enc_mw = (const float*)d_in[6],  *enc_mb = (const float*)d_in[7];
    const float *enc_sw = (const float*)d_in[8],  *enc_sb = (const float*)d_in[9];
    const float *pri_w1 = (const float*)d_in[10], *pri_b1 = (const float*)d_in[11];
    const float *pri_w2 = (const float*)d_in[12], *pri_b2 = (const float*)d_in[13];
    const float *pri_mw = (const float*)d_in[14], *pri_mb = (const float*)d_in[15];
    const float *pri_sw = (const float*)d_in[16], *pri_sb = (const float*)d_in[17];
    const float *dec_w1 = (const float*)d_in[18], *dec_b1 = (const float*)d_in[19];
    const float *dec_w2 = (const float*)d_in[20], *dec_b2 = (const float*)d_in[21];
    const float *dec_mw = (const float*)d_in[22], *dec_mb = (const float*)d_in[23];
    const float *dec_sw = (const float*)d_in[24], *dec_sb = (const float*)d_in[25];
    const float *gwih   = (const float*)d_in[26], *gwhh   = (const float*)d_in[27];
    const float *gbih   = (const float*)d_in[28], *gbhh   = (const float*)d_in[29];
    float* out = (float*)d_out;

    static bool attrSet = false;
    if (!attrSet) {
        cudaFuncSetAttribute(vrnn_main, cudaFuncAttributeMaxDynamicSharedMemorySize,
                             43520 * (int)sizeof(float));
        attrSet = true;
    }

    vrnn_prep<<<(TOTAL_PREP + 255) / 256, 256>>>(
        enc_w1, enc_b1, enc_w2, enc_b2, enc_mw, enc_mb, enc_sw, enc_sb,
        pri_w1, pri_b1, pri_w2, pri_b2, pri_mw, pri_mb, pri_sw, pri_sb,
        dec_w1, dec_b1, dec_w2, dec_b2, dec_mw, dec_mb, dec_sw, dec_sb,
        gwih, gwhh);
    vrnn_main<<<NCTA, NTHR, 43520 * sizeof(float)>>>(states, eps, gbih, gbhh, out);
}